// round 11
// baseline (speedup 1.0000x reference)
#include <cuda_runtime.h>
#include <math.h>

#define NATOMS 5000
#define NPAIRS 160000
#define KCH 128
#define FEAT 1152               /* 9 * 128 */
#define MS 0.1767767f           /* MSG_SCALE */
#define ISC 0.2f                /* INIT_SCALE */
#define SQ3 1.7320508075688772f
#define NTILES (NPAIRS / 16)

__device__ float g_feats[NATOMS * FEAT];
__device__ float g_new[NATOMS * FEAT];
__device__ float4 g_rec[NPAIRS * 4];   /* (c,n,sp,sh6)(sh1..4)(sh5,sh7,sh8,-)(-) 64B */
__device__ float4 g_rad[NPAIRS * 2];   /* radial basis, 32B */
__device__ int g_off[NATOMS];

__device__ __forceinline__ float siluf(float x) { return x / (1.f + expf(-x)); }

typedef unsigned long long u64;
__device__ __forceinline__ u64 pk2(float lo, float hi) {
    u64 r; asm("mov.b64 %0,{%1,%2};" : "=l"(r) : "f"(lo), "f"(hi)); return r;
}
__device__ __forceinline__ void upk2(float& lo, float& hi, u64 v) {
    asm("mov.b64 {%0,%1},%2;" : "=f"(lo), "=f"(hi) : "l"(v));
}
__device__ __forceinline__ void fma2(u64& d, u64 a, u64 b) {
    asm("fma.rn.f32x2 %0,%1,%2,%0;" : "+l"(d) : "l"(a), "l"(b));
}
__device__ __forceinline__ u64 mul2(u64 a, u64 b) {
    u64 r; asm("mul.rn.f32x2 %0,%1,%2;" : "=l"(r) : "l"(a), "l"(b)); return r;
}

/* ---------------- zero feats ---------------- */
__global__ void zero_kernel() {
    float4* p = (float4*)g_feats;
    const int n = NATOMS * FEAT / 4;
    const int tid = blockIdx.x * blockDim.x + threadIdx.x;
    for (int i = tid; i < n; i += gridDim.x * blockDim.x)
        p[i] = make_float4(0.f, 0.f, 0.f, 0.f);
}

/* ---------------- hist + scan in ONE single-block kernel ------------------- */
__global__ __launch_bounds__(1024)
void histscan_kernel(const int* __restrict__ ctr) {
    __shared__ int cnt[NATOMS];
    __shared__ int wsum[32];
    const int t = threadIdx.x;
    for (int i = t; i < NATOMS; i += 1024) cnt[i] = 0;
    __syncthreads();
    for (int p = t; p < NPAIRS; p += 1024) atomicAdd(&cnt[__ldg(ctr + p)], 1);
    __syncthreads();
    const int base = t * 5;
    int c[5]; int s = 0;
#pragma unroll
    for (int i = 0; i < 5; i++) {
        int idx = base + i;
        c[i] = (idx < NATOMS) ? cnt[idx] : 0;
        s += c[i];
    }
    const int lane = t & 31, wid = t >> 5;
    int v = s;
#pragma unroll
    for (int o = 1; o < 32; o <<= 1) {
        int u = __shfl_up_sync(0xffffffffu, v, o);
        if (lane >= o) v += u;
    }
    if (lane == 31) wsum[wid] = v;
    __syncthreads();
    if (wid == 0) {
        int w = wsum[lane];
#pragma unroll
        for (int o = 1; o < 32; o <<= 1) {
            int u = __shfl_up_sync(0xffffffffu, w, o);
            if (lane >= o) w += u;
        }
        wsum[lane] = w;
    }
    __syncthreads();
    int excl = v - s + ((wid > 0) ? wsum[wid - 1] : 0);
#pragma unroll
    for (int i = 0; i < 5; i++) {
        int idx = base + i;
        if (idx < NATOMS) { g_off[idx] = excl; excl += c[i]; }
    }
}

__global__ void scatter_kernel(const float* __restrict__ pos, const float* __restrict__ cells,
                               const int* __restrict__ species, const int* __restrict__ shifts,
                               const int* __restrict__ ctr, const int* __restrict__ nbr,
                               const int* __restrict__ spair)
{
    const int p = blockIdx.x * blockDim.x + threadIdx.x;
    if (p >= NPAIRS) return;
    const int c = __ldg(ctr + p);
    const int n = __ldg(nbr + p);
    const int s = __ldg(spair + p);
    const float sx = (float)__ldg(shifts + 3 * p + 0) - 1.f;
    const float sy = (float)__ldg(shifts + 3 * p + 1) - 1.f;
    const float sz = (float)__ldg(shifts + 3 * p + 2) - 1.f;
    const float* M = cells + 9 * s;
    float vx = __ldg(pos + 3 * n + 0) - __ldg(pos + 3 * c + 0) + sx * __ldg(M + 0) + sy * __ldg(M + 3) + sz * __ldg(M + 6);
    float vy = __ldg(pos + 3 * n + 1) - __ldg(pos + 3 * c + 1) + sx * __ldg(M + 1) + sy * __ldg(M + 4) + sz * __ldg(M + 7);
    float vz = __ldg(pos + 3 * n + 2) - __ldg(pos + 3 * c + 2) + sx * __ldg(M + 2) + sy * __ldg(M + 5) + sz * __ldg(M + 8);
    const float dd = vx * vx + vy * vy + vz * vz + 1e-12f;
    const float d = sqrtf(dd);
    const float id = 1.f / d;
    const float x = vx * id, y = vy * id, z = vz * id;
    const float fc = (d < 5.f) ? 0.5f * (cosf(0.6283185307179586f * d) + 1.f) : 0.f;
    float in[8];
#pragma unroll
    for (int b = 0; b < 8; b++) {
        float t = d - 0.7142857142857143f * (float)b;
        in[b] = expf(-2.f * t * t) * fc;
    }
    const int dst = atomicAdd(&g_off[c], 1);
    float4* r = g_rec + dst * 4;
    r[0] = make_float4(__int_as_float(c), __int_as_float(n), __int_as_float(__ldg(species + n)),
                       ISC * 0.5f * (3.f * z * z - 1.f));
    r[1] = make_float4(ISC * y, ISC * z, ISC * x, ISC * SQ3 * x * y);
    r[2] = make_float4(ISC * SQ3 * y * z, ISC * SQ3 * x * z,
                       ISC * 0.5f * SQ3 * (x * x - y * y), 0.f);
    float4* rr = g_rad + dst * 2;
    rr[0] = make_float4(in[0], in[1], in[2], in[3]);
    rr[1] = make_float4(in[4], in[5], in[6], in[7]);
}

/* ---------------- pair kernels: 16-pair tiles, packed f32x2 epilogue ------- */
template <int PASS>
__global__ __launch_bounds__(128, 4)
void pair_kernel(const float* __restrict__ embed,
                 const float* __restrict__ w1, const float* __restrict__ b1,
                 const float* __restrict__ w2, const float* __restrict__ b2)
{
    __shared__ float w2s[12288];
    __shared__ float w1s[256];
    __shared__ float b1s[32];
    __shared__ float b2s[384];
    __shared__ u64 hs[256];
    {
        float4* d4 = (float4*)w2s;
        const float4* s4 = (const float4*)w2;
        for (int i = threadIdx.x; i < 3072; i += 128) d4[i] = s4[i];
        for (int i = threadIdx.x; i < 256; i += 128) w1s[i] = w1[i];
        if (threadIdx.x < 32) b1s[threadIdx.x] = b1[threadIdx.x];
        for (int i = threadIdx.x; i < 384; i += 128) b2s[i] = b2[i];
    }
    __syncthreads();

    const int lane = threadIdx.x & 31;
    const int w = threadIdx.x >> 5;
    const int kb = w * 32 + lane;

    const u64 bi0 = pk2(b2s[kb], b2s[kb]);
    const u64 bi1 = pk2(b2s[128 + kb], b2s[128 + kb]);
    const u64 bi2 = pk2(b2s[256 + kb], b2s[256 + kb]);
    const u64 ISC2 = pk2(ISC, ISC);
    const u64 MS2 = pk2(MS, MS);
    const u64 C1I = pk2(1.f + ISC, 1.f + ISC);

    float e4_0 = 0.f, e4_1 = 0.f, e4_2 = 0.f, e4_3 = 0.f;
    if (PASS == 1) {
        e4_0 = __ldg(embed + 0 * KCH + kb) * MS;
        e4_1 = __ldg(embed + 1 * KCH + kb) * MS;
        e4_2 = __ldg(embed + 2 * KCH + kb) * MS;
        e4_3 = __ldg(embed + 3 * KCH + kb) * MS;
    }

    u64 accP[9];
#pragma unroll
    for (int i = 0; i < 9; i++) accP[i] = 0ull;
    int cur_c = -1;

#define FLUSHP()                                                                \
    do {                                                                        \
        float* fb = ((PASS == 1) ? g_feats : g_new) + cur_c * FEAT + kb;        \
        _Pragma("unroll")                                                       \
        for (int comp = 0; comp < 9; comp++) {                                  \
            float lo_, hi_; upk2(lo_, hi_, accP[comp]);                         \
            atomicAdd(fb + comp * KCH, lo_ + hi_);                              \
        }                                                                       \
    } while (0)

    for (int tile = blockIdx.x; tile < NTILES; tile += gridDim.x) {
        const int q0 = tile * 16;

        /* hidden layer: warp w handles pairs q0+4w .. q0+4w+3 */
        float hac[4];
#pragma unroll
        for (int pp = 0; pp < 4; pp++) {
            const float4* rr = g_rad + (q0 + 4 * w + pp) * 2;
            const float4 i0 = __ldg(rr + 0);
            const float4 i1 = __ldg(rr + 1);
            float h = b1s[lane]
                + i0.x * w1s[lane]        + i0.y * w1s[32 + lane]
                + i0.z * w1s[64 + lane]   + i0.w * w1s[96 + lane]
                + i1.x * w1s[128 + lane]  + i1.y * w1s[160 + lane]
                + i1.z * w1s[192 + lane]  + i1.w * w1s[224 + lane];
            hac[pp] = siluf(h);
        }
        hs[(2 * w + 0) * 32 + lane] = pk2(hac[0], hac[1]);
        hs[(2 * w + 1) * 32 + lane] = pk2(hac[2], hac[3]);
        __syncthreads();

        /* GEMM: 16 pairs (8 packed) x 3 rows for this warp's channels */
        u64 A0[8], A1[8], A2[8];
#pragma unroll
        for (int j = 0; j < 8; j++) { A0[j] = bi0; A1[j] = bi1; A2[j] = bi2; }
#pragma unroll 8
        for (int b = 0; b < 32; b++) {
            const float w0f = w2s[b * 384 + kb];
            const float w1f = w2s[b * 384 + 128 + kb];
            const float w2f = w2s[b * 384 + 256 + kb];
            const u64 wv0 = pk2(w0f, w0f);
            const u64 wv1 = pk2(w1f, w1f);
            const u64 wv2 = pk2(w2f, w2f);
#pragma unroll
            for (int j = 0; j < 8; j++) {
                const u64 hb = hs[j * 32 + b];
                fma2(A0[j], wv0, hb);
                fma2(A1[j], wv1, hb);
                fma2(A2[j], wv2, hb);
            }
        }

        /* epilogue: packed over pair-duos sharing a center */
#pragma unroll
        for (int j = 0; j < 8; j++) {
            const int p0 = q0 + 2 * j;
            const float4* ra = g_rec + p0 * 4;
            const float4* rb = g_rec + (p0 + 1) * 4;
            const float4 a0 = __ldg(ra + 0);
            const float4 b0 = __ldg(rb + 0);
            const int c0 = __float_as_int(a0.x);
            const int c1 = __float_as_int(b0.x);

            if (c0 == c1) {
                /* fast path: both pairs same center */
                if (c0 != cur_c) {
                    if (cur_c >= 0) FLUSHP();
                    cur_c = c0;
#pragma unroll
                    for (int i = 0; i < 9; i++) accP[i] = 0ull;
                }
                const float4 a1 = __ldg(ra + 1), b1_ = __ldg(rb + 1);
                const float4 a2 = __ldg(ra + 2), b2_ = __ldg(rb + 2);
                const u64 sh1p = pk2(a1.x, b1_.x), sh2p = pk2(a1.y, b1_.y);
                const u64 sh3p = pk2(a1.z, b1_.z), sh4p = pk2(a1.w, b1_.w);
                const u64 sh5p = pk2(a2.x, b2_.x), sh7p = pk2(a2.y, b2_.y);
                const u64 sh8p = pk2(a2.z, b2_.z), sh6p = pk2(a0.w, b0.w);

                if (PASS == 1) {
                    const int sp0 = __float_as_int(a0.z), sp1 = __float_as_int(b0.z);
                    const float ea = (sp0 == 0) ? e4_0 : (sp0 == 1) ? e4_1 : (sp0 == 2) ? e4_2 : e4_3;
                    const float eb = (sp1 == 0) ? e4_0 : (sp1 == 1) ? e4_1 : (sp1 == 2) ? e4_2 : e4_3;
                    const u64 ep = pk2(ea, eb);
                    const u64 rp0 = mul2(A0[j], ep);
                    const u64 rp1 = mul2(A1[j], ep);
                    const u64 rp2 = mul2(A2[j], ep);
                    fma2(accP[0], ISC2, rp0);
                    fma2(accP[1], sh1p, rp1);
                    fma2(accP[2], sh2p, rp1);
                    fma2(accP[3], sh3p, rp1);
                    fma2(accP[4], sh4p, rp2);
                    fma2(accP[5], sh5p, rp2);
                    fma2(accP[6], sh6p, rp2);
                    fma2(accP[7], sh7p, rp2);
                    fma2(accP[8], sh8p, rp2);
                } else {
                    const int n0 = __float_as_int(a0.y), n1 = __float_as_int(b0.y);
                    const float* gn0 = g_feats + n0 * FEAT + kb;
                    const float* gn1 = g_feats + n1 * FEAT + kb;
                    const u64 invp = pk2(__ldg(gn0), __ldg(gn1));
                    const u64 rp0 = mul2(A0[j], MS2);
                    const u64 rp1 = mul2(A1[j], MS2);
                    const u64 rp2 = mul2(A2[j], MS2);
                    const u64 t0 = mul2(rp0, invp);
                    const u64 u1 = mul2(rp1, invp);
                    const u64 u2 = mul2(rp2, invp);
                    fma2(accP[0], C1I, t0);
#pragma unroll
                    for (int cc = 1; cc < 9; cc++) {
                        const u64 gp = pk2(__ldg(gn0 + cc * KCH), __ldg(gn1 + cc * KCH));
                        fma2(accP[cc], rp0, gp);
                    }
                    fma2(accP[1], sh1p, u1);
                    fma2(accP[2], sh2p, u1);
                    fma2(accP[3], sh3p, u1);
                    fma2(accP[4], sh4p, u2);
                    fma2(accP[5], sh5p, u2);
                    fma2(accP[6], sh6p, u2);
                    fma2(accP[7], sh7p, u2);
                    fma2(accP[8], sh8p, u2);
                }
            } else {
                /* slow path: boundary inside the duo — scalar per pair */
#pragma unroll
                for (int e = 0; e < 2; e++) {
                    const float4 h0 = (e == 0) ? a0 : b0;
                    const float4* rp_ = (e == 0) ? ra : rb;
                    const int c = __float_as_int(h0.x);
                    const int n = __float_as_int(h0.y);
                    const int sp = __float_as_int(h0.z);
                    if (c != cur_c) {
                        if (cur_c >= 0) FLUSHP();
                        cur_c = c;
#pragma unroll
                        for (int i = 0; i < 9; i++) accP[i] = 0ull;
                    }
                    const float4 s1 = __ldg(rp_ + 1);
                    const float4 s2 = __ldg(rp_ + 2);
                    float rv0, rv1, rv2, dum;
                    if (e == 0) { upk2(rv0, dum, A0[j]); upk2(rv1, dum, A1[j]); upk2(rv2, dum, A2[j]); }
                    else        { upk2(dum, rv0, A0[j]); upk2(dum, rv1, A1[j]); upk2(dum, rv2, A2[j]); }
                    float v[9];
                    if (PASS == 1) {
                        const float e_ = (sp == 0) ? e4_0 : (sp == 1) ? e4_1 : (sp == 2) ? e4_2 : e4_3;
                        const float r0 = rv0 * e_, r1 = rv1 * e_, r2 = rv2 * e_;
                        v[0] = ISC * r0;
                        v[1] = s1.x * r1; v[2] = s1.y * r1; v[3] = s1.z * r1;
                        v[4] = s1.w * r2; v[5] = s2.x * r2; v[6] = h0.w * r2;
                        v[7] = s2.y * r2; v[8] = s2.z * r2;
                    } else {
                        const float r0 = rv0 * MS, r1 = rv1 * MS, r2 = rv2 * MS;
                        const float* gn = g_feats + n * FEAT + kb;
                        const float inv = __ldg(gn);
                        const float u1 = r1 * inv, u2 = r2 * inv;
                        v[0] = (1.f + ISC) * r0 * inv;
                        v[1] = s1.x * u1 + r0 * __ldg(gn + 1 * KCH);
                        v[2] = s1.y * u1 + r0 * __ldg(gn + 2 * KCH);
                        v[3] = s1.z * u1 + r0 * __ldg(gn + 3 * KCH);
                        v[4] = s1.w * u2 + r0 * __ldg(gn + 4 * KCH);
                        v[5] = s2.x * u2 + r0 * __ldg(gn + 5 * KCH);
                        v[6] = h0.w * u2 + r0 * __ldg(gn + 6 * KCH);
                        v[7] = s2.y * u2 + r0 * __ldg(gn + 7 * KCH);
                        v[8] = s2.z * u2 + r0 * __ldg(gn + 8 * KCH);
                    }
#pragma unroll
                    for (int cc = 0; cc < 9; cc++) {
                        float lo_, hi_; upk2(lo_, hi_, accP[cc]);
                        accP[cc] = pk2(lo_ + v[cc], hi_);
                    }
                }
            }
        }
        __syncthreads();   /* protect hs before next tile's stores */
    }
    if (cur_c >= 0) FLUSHP();
#undef FLUSHP
}

/* ---------------- CG tensor-square iterate (per atom, per k) ---------------- */
template <int BUF>
__global__ __launch_bounds__(128)
void cg_kernel(const float* __restrict__ mix, const float* __restrict__ U2g)
{
    __shared__ float U[81];
    const int k = threadIdx.x;
    if (k < 81) U[k] = U2g[k];
    __syncthreads();
    float* base = ((BUF == 0) ? g_feats : g_new) + blockIdx.x * FEAT + k;
    float* dup  = g_new + blockIdx.x * FEAT + k;

    {
        const float f0 = base[0];
        const float v = f0 + __ldg(mix + k) * f0 * f0;
        base[0] = v;
        if (BUF == 0) dup[0] = v;
    }
    {
        float f1[3];
#pragma unroll
        for (int j = 0; j < 3; j++) f1[j] = base[(1 + j) * KCH];
        float Mv[9];
#pragma unroll
        for (int q = 0; q < 9; q++)
            Mv[q] = U[9 + q] * f1[0] + U[18 + q] * f1[1] + U[27 + q] * f1[2];
        float Cm[9];
#pragma unroll
        for (int i = 0; i < 3; i++)
#pragma unroll
            for (int j = 0; j < 3; j++)
                Cm[3 * i + j] = Mv[3 * i] * Mv[j] + Mv[3 * i + 1] * Mv[3 + j] + Mv[3 * i + 2] * Mv[6 + j];
        const float m1 = __ldg(mix + KCH + k);
        float B[9];
#pragma unroll
        for (int q = 0; q < 9; q++) B[q] = Mv[q] + m1 * Cm[q];
#pragma unroll
        for (int j = 0; j < 3; j++) {
            float o = 0.f;
#pragma unroll
            for (int q = 0; q < 9; q++) o += U[(1 + j) * 9 + q] * B[q];
            base[(1 + j) * KCH] = o;
            if (BUF == 0) dup[(1 + j) * KCH] = o;
        }
    }
    {
        float f2[5];
#pragma unroll
        for (int j = 0; j < 5; j++) f2[j] = base[(4 + j) * KCH];
        float Mv[9];
#pragma unroll
        for (int q = 0; q < 9; q++)
            Mv[q] = U[36 + q] * f2[0] + U[45 + q] * f2[1] + U[54 + q] * f2[2] + U[63 + q] * f2[3] + U[72 + q] * f2[4];
        float Cm[9];
#pragma unroll
        for (int i = 0; i < 3; i++)
#pragma unroll
            for (int j = 0; j < 3; j++)
                Cm[3 * i + j] = Mv[3 * i] * Mv[j] + Mv[3 * i + 1] * Mv[3 + j] + Mv[3 * i + 2] * Mv[6 + j];
        const float m2 = __ldg(mix + 2 * KCH + k);
        float B[9];
#pragma unroll
        for (int q = 0; q < 9; q++) B[q] = Mv[q] + m2 * Cm[q];
#pragma unroll
        for (int j = 0; j < 5; j++) {
            float o = 0.f;
#pragma unroll
            for (int q = 0; q < 9; q++) o += U[(4 + j) * 9 + q] * B[q];
            base[(4 + j) * KCH] = o;
            if (BUF == 0) dup[(4 + j) * KCH] = o;
        }
    }
}

/* ---------------- head MLP: 20 atoms per block ---------------- */
#define APB 20
__global__ __launch_bounds__(128)
void head_kernel(const float* __restrict__ hw1, const float* __restrict__ hb1,
                 const float* __restrict__ hw2, const float* __restrict__ hb2,
                 const float* __restrict__ lw, const float* __restrict__ lb,
                 float* __restrict__ out)
{
    __shared__ float hs[APB][132];
    const int a0 = blockIdx.x * APB;
    const int j = threadIdx.x;

    for (int i = 0; i < APB; i++) hs[i][j] = g_new[(a0 + i) * FEAT + j];
    __syncthreads();

    float acc[APB];
    {
        const float b = __ldg(hb1 + j);
#pragma unroll
        for (int i = 0; i < APB; i++) acc[i] = b;
    }
    for (int kk = 0; kk < 128; kk++) {
        const float w = __ldg(hw1 + kk * 128 + j);
#pragma unroll
        for (int i = 0; i < APB; i++) acc[i] += hs[i][kk] * w;
    }
    __syncthreads();
#pragma unroll
    for (int i = 0; i < APB; i++) hs[i][j] = siluf(acc[i]);
    __syncthreads();
    {
        const float b = __ldg(hb2 + j);
#pragma unroll
        for (int i = 0; i < APB; i++) acc[i] = b;
    }
    for (int kk = 0; kk < 128; kk++) {
        const float w = __ldg(hw2 + kk * 128 + j);
#pragma unroll
        for (int i = 0; i < APB; i++) acc[i] += hs[i][kk] * w;
    }
    __syncthreads();
    {
        const float lwj = __ldg(lw + j);
#pragma unroll
        for (int i = 0; i < APB; i++) hs[i][j] = siluf(acc[i]) * lwj;
    }
    __syncthreads();
    if (j < APB) {
        float s = __ldg(lb);
        for (int q = 0; q < 128; q++) s += hs[j][q];
        out[a0 + j] = s;
    }
}

extern "C" void kernel_launch(void* const* d_in, const int* in_sizes, int n_in,
                              void* d_out, int out_size)
{
    const float* pos     = (const float*)d_in[0];
    const float* cells   = (const float*)d_in[1];
    const int*   species = (const int*)d_in[2];
    const int*   shifts  = (const int*)d_in[3];
    const int*   ctr     = (const int*)d_in[4];
    const int*   nbr     = (const int*)d_in[5];
    const int*   spair   = (const int*)d_in[6];
    const float* embed   = (const float*)d_in[7];
    const float* rw1 = (const float*)d_in[8];
    const float* rb1 = (const float*)d_in[9];
    const float* rw2 = (const float*)d_in[10];
    const float* rb2 = (const float*)d_in[11];
    const float* ew1 = (const float*)d_in[12];
    const float* eb1 = (const float*)d_in[13];
    const float* ew2 = (const float*)d_in[14];
    const float* eb2 = (const float*)d_in[15];
    const float* mixa  = (const float*)d_in[16];
    const float* emixa = (const float*)d_in[17];
    const float* hw1 = (const float*)d_in[18];
    const float* hb1 = (const float*)d_in[19];
    const float* hw2 = (const float*)d_in[20];
    const float* hb2 = (const float*)d_in[21];
    const float* lw  = (const float*)d_in[22];
    const float* lb  = (const float*)d_in[23];
    const float* U2  = (const float*)d_in[24];
    float* out = (float*)d_out;

    zero_kernel<<<1024, 256>>>();
    histscan_kernel<<<1, 1024>>>(ctr);
    scatter_kernel<<<(NPAIRS + 255) / 256, 256>>>(pos, cells, species, shifts, ctr, nbr, spair);
    pair_kernel<1><<<592, 128>>>(embed, rw1, rb1, rw2, rb2);   /* launch idx 3 -> ncu capture */
    cg_kernel<0><<<NATOMS, 128>>>(mixa, U2);
    pair_kernel<2><<<592, 128>>>(embed, ew1, eb1, ew2, eb2);
    cg_kernel<1><<<NATOMS, 128>>>(emixa, U2);
    head_kernel<<<NATOMS / APB, 128>>>(hw1, hb1, hw2, hb2, lw, lb, out);
}

// round 12
// speedup vs baseline: 1.0083x; 1.0083x over previous
#include <cuda_runtime.h>
#include <math.h>

#define NATOMS 5000
#define NPAIRS 160000
#define KCH 128
#define FEAT 1152               /* 9 * 128 */
#define MS 0.1767767f           /* MSG_SCALE */
#define ISC 0.2f                /* INIT_SCALE */
#define SQ3 1.7320508075688772f
#define NTILES (NPAIRS / 16)

__device__ float g_feats[NATOMS * FEAT];
__device__ float g_new[NATOMS * FEAT];
__device__ float4 g_rec[NPAIRS * 4];   /* sorted pair records, 64B each */
__device__ int g_off[NATOMS];

__device__ __forceinline__ float siluf(float x) { return x / (1.f + expf(-x)); }

typedef unsigned long long u64;
__device__ __forceinline__ u64 pk2(float lo, float hi) {
    u64 r; asm("mov.b64 %0,{%1,%2};" : "=l"(r) : "f"(lo), "f"(hi)); return r;
}
__device__ __forceinline__ void upk2(float& lo, float& hi, u64 v) {
    asm("mov.b64 {%0,%1},%2;" : "=f"(lo), "=f"(hi) : "l"(v));
}
__device__ __forceinline__ void fma2(u64& d, u64 a, u64 b) {
    asm("fma.rn.f32x2 %0,%1,%2,%0;" : "+l"(d) : "l"(a), "l"(b));
}

/* ---------------- zero feats ---------------- */
__global__ void zero_kernel() {
    float4* p = (float4*)g_feats;
    const int n = NATOMS * FEAT / 4;
    const int tid = blockIdx.x * blockDim.x + threadIdx.x;
    for (int i = tid; i < n; i += gridDim.x * blockDim.x)
        p[i] = make_float4(0.f, 0.f, 0.f, 0.f);
}

/* ---------------- hist + scan in ONE single-block kernel ------------------- */
__global__ __launch_bounds__(1024)
void histscan_kernel(const int* __restrict__ ctr) {
    __shared__ int cnt[NATOMS];
    __shared__ int wsum[32];
    const int t = threadIdx.x;
    for (int i = t; i < NATOMS; i += 1024) cnt[i] = 0;
    __syncthreads();
    for (int p = t; p < NPAIRS; p += 1024) atomicAdd(&cnt[__ldg(ctr + p)], 1);
    __syncthreads();
    const int base = t * 5;
    int c[5]; int s = 0;
#pragma unroll
    for (int i = 0; i < 5; i++) {
        int idx = base + i;
        c[i] = (idx < NATOMS) ? cnt[idx] : 0;
        s += c[i];
    }
    const int lane = t & 31, wid = t >> 5;
    int v = s;
#pragma unroll
    for (int o = 1; o < 32; o <<= 1) {
        int u = __shfl_up_sync(0xffffffffu, v, o);
        if (lane >= o) v += u;
    }
    if (lane == 31) wsum[wid] = v;
    __syncthreads();
    if (wid == 0) {
        int w = wsum[lane];
#pragma unroll
        for (int o = 1; o < 32; o <<= 1) {
            int u = __shfl_up_sync(0xffffffffu, w, o);
            if (lane >= o) w += u;
        }
        wsum[lane] = w;
    }
    __syncthreads();
    int excl = v - s + ((wid > 0) ? wsum[wid - 1] : 0);
#pragma unroll
    for (int i = 0; i < 5; i++) {
        int idx = base + i;
        if (idx < NATOMS) { g_off[idx] = excl; excl += c[i]; }
    }
}

__global__ void scatter_kernel(const float* __restrict__ pos, const float* __restrict__ cells,
                               const int* __restrict__ species, const int* __restrict__ shifts,
                               const int* __restrict__ ctr, const int* __restrict__ nbr,
                               const int* __restrict__ spair)
{
    const int p = blockIdx.x * blockDim.x + threadIdx.x;
    if (p >= NPAIRS) return;
    const int c = __ldg(ctr + p);
    const int n = __ldg(nbr + p);
    const int s = __ldg(spair + p);
    const float sx = (float)__ldg(shifts + 3 * p + 0) - 1.f;
    const float sy = (float)__ldg(shifts + 3 * p + 1) - 1.f;
    const float sz = (float)__ldg(shifts + 3 * p + 2) - 1.f;
    const float* M = cells + 9 * s;
    float vx = __ldg(pos + 3 * n + 0) - __ldg(pos + 3 * c + 0) + sx * __ldg(M + 0) + sy * __ldg(M + 3) + sz * __ldg(M + 6);
    float vy = __ldg(pos + 3 * n + 1) - __ldg(pos + 3 * c + 1) + sx * __ldg(M + 1) + sy * __ldg(M + 4) + sz * __ldg(M + 7);
    float vz = __ldg(pos + 3 * n + 2) - __ldg(pos + 3 * c + 2) + sx * __ldg(M + 2) + sy * __ldg(M + 5) + sz * __ldg(M + 8);
    const float dd = vx * vx + vy * vy + vz * vz + 1e-12f;
    const float d = sqrtf(dd);
    const float id = 1.f / d;
    const float fc = (d < 5.f) ? 0.5f * (cosf(0.6283185307179586f * d) + 1.f) : 0.f;
    float in[8];
#pragma unroll
    for (int b = 0; b < 8; b++) {
        float t = d - 0.7142857142857143f * (float)b;
        in[b] = expf(-2.f * t * t) * fc;
    }
    const int dst = atomicAdd(&g_off[c], 1);
    float4* r = g_rec + dst * 4;
    r[0] = make_float4(__int_as_float(c), __int_as_float(n), __int_as_float(__ldg(species + n)), d);
    r[1] = make_float4(vx * id, vy * id, vz * id, 0.f);
    r[2] = make_float4(in[0], in[1], in[2], in[3]);
    r[3] = make_float4(in[4], in[5], in[6], in[7]);
}

/* ---------------- pair kernels: 256-thread blocks, 24 warps/SM -------------
 * Tile = 16 pairs. Warp w (0..7): channel subgroup kb=(w&3)*32+lane, pair
 * half hf=w>>2 (pairs 8hf..8hf+7, packed pairpairs jj=4hf..4hf+3).
 * hs pairpair-major (round-6 proven layout), double-buffered -> 1 sync/tile.
 */
template <int PASS>
__global__ __launch_bounds__(256, 3)
void pair_kernel(const float* __restrict__ embed,
                 const float* __restrict__ w1, const float* __restrict__ b1,
                 const float* __restrict__ w2, const float* __restrict__ b2)
{
    __shared__ float w2s[12288];
    __shared__ float w1s[256];
    __shared__ float b1s[32];
    __shared__ float b2s[384];
    __shared__ u64 hs[2][256];     /* [buf][pairpair 0..7][unit b 0..31] */
    {
        float4* d4 = (float4*)w2s;
        const float4* s4 = (const float4*)w2;
        for (int i = threadIdx.x; i < 3072; i += 256) d4[i] = s4[i];
        if (threadIdx.x < 256) w1s[threadIdx.x] = w1[threadIdx.x];
        if (threadIdx.x < 32) b1s[threadIdx.x] = b1[threadIdx.x];
        for (int i = threadIdx.x; i < 384; i += 256) b2s[i] = b2[i];
    }
    __syncthreads();

    const int lane = threadIdx.x & 31;
    const int w = threadIdx.x >> 5;        /* 0..7 */
    const int hf = w >> 2;                 /* pair half */
    const int kb = (w & 3) * 32 + lane;    /* owned channel */

    const u64 bi0 = pk2(b2s[kb], b2s[kb]);
    const u64 bi1 = pk2(b2s[128 + kb], b2s[128 + kb]);
    const u64 bi2 = pk2(b2s[256 + kb], b2s[256 + kb]);

    float e4_0 = 0.f, e4_1 = 0.f, e4_2 = 0.f, e4_3 = 0.f;
    if (PASS == 1) {
        e4_0 = __ldg(embed + 0 * KCH + kb) * MS;
        e4_1 = __ldg(embed + 1 * KCH + kb) * MS;
        e4_2 = __ldg(embed + 2 * KCH + kb) * MS;
        e4_3 = __ldg(embed + 3 * KCH + kb) * MS;
    }

    float accE[9];
#pragma unroll
    for (int i = 0; i < 9; i++) accE[i] = 0.f;
    int cur_c = -1;

#define FLUSHE()                                                                \
    do {                                                                        \
        float* fb = ((PASS == 1) ? g_feats : g_new) + cur_c * FEAT + kb;        \
        _Pragma("unroll")                                                       \
        for (int comp = 0; comp < 9; comp++)                                    \
            atomicAdd(fb + comp * KCH, accE[comp]);                             \
    } while (0)

    int buf = 0;
    for (int tile = blockIdx.x; tile < NTILES; tile += gridDim.x, buf ^= 1) {
        const int q0 = tile * 16;

        /* hidden layer: warp w handles pairs q0+2w, q0+2w+1; lane = unit b */
        float hac[2];
#pragma unroll
        for (int pp = 0; pp < 2; pp++) {
            const float4* r = g_rec + (q0 + 2 * w + pp) * 4;
            const float4 i0 = __ldg(r + 2);
            const float4 i1 = __ldg(r + 3);
            float h = b1s[lane]
                + i0.x * w1s[lane]        + i0.y * w1s[32 + lane]
                + i0.z * w1s[64 + lane]   + i0.w * w1s[96 + lane]
                + i1.x * w1s[128 + lane]  + i1.y * w1s[160 + lane]
                + i1.z * w1s[192 + lane]  + i1.w * w1s[224 + lane];
            hac[pp] = siluf(h);
        }
        hs[buf][w * 32 + lane] = pk2(hac[0], hac[1]);   /* pairpair w */
        __syncthreads();

        /* GEMM: 4 packed pairpairs (jj=4hf..4hf+3) x 3 rows for kb */
        u64 A0[4], A1[4], A2[4];
#pragma unroll
        for (int j = 0; j < 4; j++) { A0[j] = bi0; A1[j] = bi1; A2[j] = bi2; }
        const u64* hb_base = hs[buf] + 4 * hf * 32;
#pragma unroll 8
        for (int b = 0; b < 32; b++) {
            const float w0f = w2s[b * 384 + kb];
            const float w1f = w2s[b * 384 + 128 + kb];
            const float w2f = w2s[b * 384 + 256 + kb];
            const u64 wv0 = pk2(w0f, w0f);
            const u64 wv1 = pk2(w1f, w1f);
            const u64 wv2 = pk2(w2f, w2f);
#pragma unroll
            for (int j = 0; j < 4; j++) {
                const u64 hb = hb_base[j * 32 + b];
                fma2(A0[j], wv0, hb);
                fma2(A1[j], wv1, hb);
                fma2(A2[j], wv2, hb);
            }
        }

        /* epilogue: 8 pairs (p = q0 + 8hf .. q0 + 8hf+7), owned channel kb */
#pragma unroll
        for (int j = 0; j < 4; j++) {
            float r0v[2], r1v[2], r2v[2];
            upk2(r0v[0], r0v[1], A0[j]);
            upk2(r1v[0], r1v[1], A1[j]);
            upk2(r2v[0], r2v[1], A2[j]);
#pragma unroll
            for (int e = 0; e < 2; e++) {
                const int p = q0 + 2 * (4 * hf + j) + e;
                const float4* r = g_rec + p * 4;
                const float4 a0 = __ldg(r + 0);
                const float4 uu = __ldg(r + 1);
                const int c = __float_as_int(a0.x);
                const int n = __float_as_int(a0.y);
                const int sp = __float_as_int(a0.z);
                const float x = uu.x, y = uu.y, z = uu.z;

                if (c != cur_c) {
                    if (cur_c >= 0) FLUSHE();
                    cur_c = c;
#pragma unroll
                    for (int i = 0; i < 9; i++) accE[i] = 0.f;
                }

                const float sh1 = ISC * y, sh2 = ISC * z, sh3 = ISC * x;
                const float sh4 = ISC * SQ3 * x * y;
                const float sh5 = ISC * SQ3 * y * z;
                const float sh6 = ISC * 0.5f * (3.f * z * z - 1.f);
                const float sh7 = ISC * SQ3 * x * z;
                const float sh8 = ISC * 0.5f * SQ3 * (x * x - y * y);

                if (PASS == 1) {
                    const float e_ = (sp == 0) ? e4_0 : (sp == 1) ? e4_1 : (sp == 2) ? e4_2 : e4_3;
                    const float r0 = r0v[e] * e_, r1 = r1v[e] * e_, r2 = r2v[e] * e_;
                    accE[0] += ISC * r0;
                    accE[1] += sh1 * r1;
                    accE[2] += sh2 * r1;
                    accE[3] += sh3 * r1;
                    accE[4] += sh4 * r2;
                    accE[5] += sh5 * r2;
                    accE[6] += sh6 * r2;
                    accE[7] += sh7 * r2;
                    accE[8] += sh8 * r2;
                } else {
                    const float r0 = r0v[e] * MS, r1 = r1v[e] * MS, r2 = r2v[e] * MS;
                    const float* gn = g_feats + n * FEAT;
                    const float inv = __ldg(gn + kb);
                    const float u1 = r1 * inv, u2 = r2 * inv;
                    accE[0] += ISC * r0 * inv + r0 * inv;
                    accE[1] += sh1 * u1 + r0 * __ldg(gn + 1 * KCH + kb);
                    accE[2] += sh2 * u1 + r0 * __ldg(gn + 2 * KCH + kb);
                    accE[3] += sh3 * u1 + r0 * __ldg(gn + 3 * KCH + kb);
                    accE[4] += sh4 * u2 + r0 * __ldg(gn + 4 * KCH + kb);
                    accE[5] += sh5 * u2 + r0 * __ldg(gn + 5 * KCH + kb);
                    accE[6] += sh6 * u2 + r0 * __ldg(gn + 6 * KCH + kb);
                    accE[7] += sh7 * u2 + r0 * __ldg(gn + 7 * KCH + kb);
                    accE[8] += sh8 * u2 + r0 * __ldg(gn + 8 * KCH + kb);
                }
            }
        }
        /* no trailing sync: next tile writes the other hs buffer */
    }
    if (cur_c >= 0) FLUSHE();
#undef FLUSHE
}

/* ---------------- CG tensor-square iterate (per atom, per k) ---------------- */
template <int BUF>
__global__ __launch_bounds__(128)
void cg_kernel(const float* __restrict__ mix, const float* __restrict__ U2g)
{
    __shared__ float U[81];
    const int k = threadIdx.x;
    if (k < 81) U[k] = U2g[k];
    __syncthreads();
    float* base = ((BUF == 0) ? g_feats : g_new) + blockIdx.x * FEAT + k;
    float* dup  = g_new + blockIdx.x * FEAT + k;

    {
        const float f0 = base[0];
        const float v = f0 + __ldg(mix + k) * f0 * f0;
        base[0] = v;
        if (BUF == 0) dup[0] = v;
    }
    {
        float f1[3];
#pragma unroll
        for (int j = 0; j < 3; j++) f1[j] = base[(1 + j) * KCH];
        float Mv[9];
#pragma unroll
        for (int q = 0; q < 9; q++)
            Mv[q] = U[9 + q] * f1[0] + U[18 + q] * f1[1] + U[27 + q] * f1[2];
        float Cm[9];
#pragma unroll
        for (int i = 0; i < 3; i++)
#pragma unroll
            for (int j = 0; j < 3; j++)
                Cm[3 * i + j] = Mv[3 * i] * Mv[j] + Mv[3 * i + 1] * Mv[3 + j] + Mv[3 * i + 2] * Mv[6 + j];
        const float m1 = __ldg(mix + KCH + k);
        float B[9];
#pragma unroll
        for (int q = 0; q < 9; q++) B[q] = Mv[q] + m1 * Cm[q];
#pragma unroll
        for (int j = 0; j < 3; j++) {
            float o = 0.f;
#pragma unroll
            for (int q = 0; q < 9; q++) o += U[(1 + j) * 9 + q] * B[q];
            base[(1 + j) * KCH] = o;
            if (BUF == 0) dup[(1 + j) * KCH] = o;
        }
    }
    {
        float f2[5];
#pragma unroll
        for (int j = 0; j < 5; j++) f2[j] = base[(4 + j) * KCH];
        float Mv[9];
#pragma unroll
        for (int q = 0; q < 9; q++)
            Mv[q] = U[36 + q] * f2[0] + U[45 + q] * f2[1] + U[54 + q] * f2[2] + U[63 + q] * f2[3] + U[72 + q] * f2[4];
        float Cm[9];
#pragma unroll
        for (int i = 0; i < 3; i++)
#pragma unroll
            for (int j = 0; j < 3; j++)
                Cm[3 * i + j] = Mv[3 * i] * Mv[j] + Mv[3 * i + 1] * Mv[3 + j] + Mv[3 * i + 2] * Mv[6 + j];
        const float m2 = __ldg(mix + 2 * KCH + k);
        float B[9];
#pragma unroll
        for (int q = 0; q < 9; q++) B[q] = Mv[q] + m2 * Cm[q];
#pragma unroll
        for (int j = 0; j < 5; j++) {
            float o = 0.f;
#pragma unroll
            for (int q = 0; q < 9; q++) o += U[(4 + j) * 9 + q] * B[q];
            base[(4 + j) * KCH] = o;
            if (BUF == 0) dup[(4 + j) * KCH] = o;
        }
    }
}

/* ---------------- head MLP: 20 atoms per block ---------------- */
#define APB 20
__global__ __launch_bounds__(128)
void head_kernel(const float* __restrict__ hw1, const float* __restrict__ hb1,
                 const float* __restrict__ hw2, const float* __restrict__ hb2,
                 const float* __restrict__ lw, const float* __restrict__ lb,
                 float* __restrict__ out)
{
    __shared__ float hs[APB][132];
    const int a0 = blockIdx.x * APB;
    const int j = threadIdx.x;

    for (int i = 0; i < APB; i++) hs[i][j] = g_new[(a0 + i) * FEAT + j];
    __syncthreads();

    float acc[APB];
    {
        const float b = __ldg(hb1 + j);
#pragma unroll
        for (int i = 0; i < APB; i++) acc[i] = b;
    }
    for (int kk = 0; kk < 128; kk++) {
        const float w = __ldg(hw1 + kk * 128 + j);
#pragma unroll
        for (int i = 0; i < APB; i++) acc[i] += hs[i][kk] * w;
    }
    __syncthreads();
#pragma unroll
    for (int i = 0; i < APB; i++) hs[i][j] = siluf(acc[i]);
    __syncthreads();
    {
        const float b = __ldg(hb2 + j);
#pragma unroll
        for (int i = 0; i < APB; i++) acc[i] = b;
    }
    for (int kk = 0; kk < 128; kk++) {
        const float w = __ldg(hw2 + kk * 128 + j);
#pragma unroll
        for (int i = 0; i < APB; i++) acc[i] += hs[i][kk] * w;
    }
    __syncthreads();
    {
        const float lwj = __ldg(lw + j);
#pragma unroll
        for (int i = 0; i < APB; i++) hs[i][j] = siluf(acc[i]) * lwj;
    }
    __syncthreads();
    if (j < APB) {
        float s = __ldg(lb);
        for (int q = 0; q < 128; q++) s += hs[j][q];
        out[a0 + j] = s;
    }
}

extern "C" void kernel_launch(void* const* d_in, const int* in_sizes, int n_in,
                              void* d_out, int out_size)
{
    const float* pos     = (const float*)d_in[0];
    const float* cells   = (const float*)d_in[1];
    const int*   species = (const int*)d_in[2];
    const int*   shifts  = (const int*)d_in[3];
    const int*   ctr     = (const int*)d_in[4];
    const int*   nbr     = (const int*)d_in[5];
    const int*   spair   = (const int*)d_in[6];
    const float* embed   = (const float*)d_in[7];
    const float* rw1 = (const float*)d_in[8];
    const float* rb1 = (const float*)d_in[9];
    const float* rw2 = (const float*)d_in[10];
    const float* rb2 = (const float*)d_in[11];
    const float* ew1 = (const float*)d_in[12];
    const float* eb1 = (const float*)d_in[13];
    const float* ew2 = (const float*)d_in[14];
    const float* eb2 = (const float*)d_in[15];
    const float* mixa  = (const float*)d_in[16];
    const float* emixa = (const float*)d_in[17];
    const float* hw1 = (const float*)d_in[18];
    const float* hb1 = (const float*)d_in[19];
    const float* hw2 = (const float*)d_in[20];
    const float* hb2 = (const float*)d_in[21];
    const float* lw  = (const float*)d_in[22];
    const float* lb  = (const float*)d_in[23];
    const float* U2  = (const float*)d_in[24];
    float* out = (float*)d_out;

    zero_kernel<<<1024, 256>>>();
    histscan_kernel<<<1, 1024>>>(ctr);
    scatter_kernel<<<(NPAIRS + 255) / 256, 256>>>(pos, cells, species, shifts, ctr, nbr, spair);
    pair_kernel<1><<<444, 256>>>(embed, rw1, rb1, rw2, rb2);   /* launch idx 3 -> ncu capture */
    cg_kernel<0><<<NATOMS, 128>>>(mixa, U2);
    pair_kernel<2><<<444, 256>>>(embed, ew1, eb1, ew2, eb2);
    cg_kernel<1><<<NATOMS, 128>>>(emixa, U2);
    head_kernel<<<NATOMS / APB, 128>>>(hw1, hb1, hw2, hb2, lw, lb, out);
}

// round 13
// speedup vs baseline: 1.2001x; 1.1903x over previous
#include <cuda_runtime.h>
#include <math.h>

#define NATOMS 5000
#define NPAIRS 160000
#define KCH 128
#define FEAT 1152               /* 9 * 128 */
#define MS 0.1767767f           /* MSG_SCALE */
#define ISC 0.2f                /* INIT_SCALE */
#define SQ3 1.7320508075688772f
#define NTILES (NPAIRS / 16)

__device__ float g_feats[NATOMS * FEAT];
__device__ float g_new[NATOMS * FEAT];
__device__ float4 g_rec[NPAIRS * 3];   /* (c,n,sp,sh6)(sh1..4)(sh5,sh7,sh8,-) 48B */
__device__ float4 g_rad[NPAIRS * 2];   /* radial basis, 32B */
__device__ int g_off[NATOMS];

__device__ __forceinline__ float siluf(float x) { return x / (1.f + expf(-x)); }

typedef unsigned long long u64;
__device__ __forceinline__ u64 pk2(float lo, float hi) {
    u64 r; asm("mov.b64 %0,{%1,%2};" : "=l"(r) : "f"(lo), "f"(hi)); return r;
}
__device__ __forceinline__ void upk2(float& lo, float& hi, u64 v) {
    asm("mov.b64 {%0,%1},%2;" : "=f"(lo), "=f"(hi) : "l"(v));
}
__device__ __forceinline__ void fma2(u64& d, u64 a, u64 b) {
    asm("fma.rn.f32x2 %0,%1,%2,%0;" : "+l"(d) : "l"(a), "l"(b));
}

/* ---------------- zero feats ---------------- */
__global__ void zero_kernel() {
    float4* p = (float4*)g_feats;
    const int n = NATOMS * FEAT / 4;
    const int tid = blockIdx.x * blockDim.x + threadIdx.x;
    for (int i = tid; i < n; i += gridDim.x * blockDim.x)
        p[i] = make_float4(0.f, 0.f, 0.f, 0.f);
}

/* ---------------- hist + scan in ONE single-block kernel ------------------- */
__global__ __launch_bounds__(1024)
void histscan_kernel(const int* __restrict__ ctr) {
    __shared__ int cnt[NATOMS];
    __shared__ int wsum[32];
    const int t = threadIdx.x;
    for (int i = t; i < NATOMS; i += 1024) cnt[i] = 0;
    __syncthreads();
    for (int p = t; p < NPAIRS; p += 1024) atomicAdd(&cnt[__ldg(ctr + p)], 1);
    __syncthreads();
    const int base = t * 5;
    int c[5]; int s = 0;
#pragma unroll
    for (int i = 0; i < 5; i++) {
        int idx = base + i;
        c[i] = (idx < NATOMS) ? cnt[idx] : 0;
        s += c[i];
    }
    const int lane = t & 31, wid = t >> 5;
    int v = s;
#pragma unroll
    for (int o = 1; o < 32; o <<= 1) {
        int u = __shfl_up_sync(0xffffffffu, v, o);
        if (lane >= o) v += u;
    }
    if (lane == 31) wsum[wid] = v;
    __syncthreads();
    if (wid == 0) {
        int w = wsum[lane];
#pragma unroll
        for (int o = 1; o < 32; o <<= 1) {
            int u = __shfl_up_sync(0xffffffffu, w, o);
            if (lane >= o) w += u;
        }
        wsum[lane] = w;
    }
    __syncthreads();
    int excl = v - s + ((wid > 0) ? wsum[wid - 1] : 0);
#pragma unroll
    for (int i = 0; i < 5; i++) {
        int idx = base + i;
        if (idx < NATOMS) { g_off[idx] = excl; excl += c[i]; }
    }
}

__global__ void scatter_kernel(const float* __restrict__ pos, const float* __restrict__ cells,
                               const int* __restrict__ species, const int* __restrict__ shifts,
                               const int* __restrict__ ctr, const int* __restrict__ nbr,
                               const int* __restrict__ spair)
{
    const int p = blockIdx.x * blockDim.x + threadIdx.x;
    if (p >= NPAIRS) return;
    const int c = __ldg(ctr + p);
    const int n = __ldg(nbr + p);
    const int s = __ldg(spair + p);
    const float sx = (float)__ldg(shifts + 3 * p + 0) - 1.f;
    const float sy = (float)__ldg(shifts + 3 * p + 1) - 1.f;
    const float sz = (float)__ldg(shifts + 3 * p + 2) - 1.f;
    const float* M = cells + 9 * s;
    float vx = __ldg(pos + 3 * n + 0) - __ldg(pos + 3 * c + 0) + sx * __ldg(M + 0) + sy * __ldg(M + 3) + sz * __ldg(M + 6);
    float vy = __ldg(pos + 3 * n + 1) - __ldg(pos + 3 * c + 1) + sx * __ldg(M + 1) + sy * __ldg(M + 4) + sz * __ldg(M + 7);
    float vz = __ldg(pos + 3 * n + 2) - __ldg(pos + 3 * c + 2) + sx * __ldg(M + 2) + sy * __ldg(M + 5) + sz * __ldg(M + 8);
    const float dd = vx * vx + vy * vy + vz * vz + 1e-12f;
    const float d = sqrtf(dd);
    const float id = 1.f / d;
    const float x = vx * id, y = vy * id, z = vz * id;
    const float fc = (d < 5.f) ? 0.5f * (cosf(0.6283185307179586f * d) + 1.f) : 0.f;
    float in[8];
#pragma unroll
    for (int b = 0; b < 8; b++) {
        float t = d - 0.7142857142857143f * (float)b;
        in[b] = expf(-2.f * t * t) * fc;
    }
    const int dst = atomicAdd(&g_off[c], 1);
    float4* r = g_rec + dst * 3;
    r[0] = make_float4(__int_as_float(c), __int_as_float(n), __int_as_float(__ldg(species + n)),
                       ISC * 0.5f * (3.f * z * z - 1.f));                 /* sh6 */
    r[1] = make_float4(ISC * y, ISC * z, ISC * x, ISC * SQ3 * x * y);     /* sh1..sh4 */
    r[2] = make_float4(ISC * SQ3 * y * z, ISC * SQ3 * x * z,
                       ISC * 0.5f * SQ3 * (x * x - y * y), 0.f);          /* sh5,sh7,sh8 */
    float4* rr = g_rad + dst * 2;
    rr[0] = make_float4(in[0], in[1], in[2], in[3]);
    rr[1] = make_float4(in[4], in[5], in[6], in[7]);
}

/* ---------------- pair kernels: 16-pair tiles, smem-staged records --------- */
template <int PASS>
__global__ __launch_bounds__(128, 4)
void pair_kernel(const float* __restrict__ embed,
                 const float* __restrict__ w1, const float* __restrict__ b1,
                 const float* __restrict__ w2, const float* __restrict__ b2)
{
    __shared__ float w2s[12288];
    __shared__ float w1s[256];
    __shared__ float b1s[32];
    __shared__ float b2s[384];
    __shared__ u64 hs[256];          /* [pairpair 0..7][unit b 0..31] */
    __shared__ float4 recs[48];      /* [pair 0..15][part 0..2] */
    {
        float4* d4 = (float4*)w2s;
        const float4* s4 = (const float4*)w2;
        for (int i = threadIdx.x; i < 3072; i += 128) d4[i] = s4[i];
        for (int i = threadIdx.x; i < 256; i += 128) w1s[i] = w1[i];
        if (threadIdx.x < 32) b1s[threadIdx.x] = b1[threadIdx.x];
        for (int i = threadIdx.x; i < 384; i += 128) b2s[i] = b2[i];
    }
    __syncthreads();

    const int lane = threadIdx.x & 31;
    const int w = threadIdx.x >> 5;
    const int kb = w * 32 + lane;      /* channel owned by this thread */

    const u64 bi0 = pk2(b2s[kb], b2s[kb]);
    const u64 bi1 = pk2(b2s[128 + kb], b2s[128 + kb]);
    const u64 bi2 = pk2(b2s[256 + kb], b2s[256 + kb]);

    float e4_0 = 0.f, e4_1 = 0.f, e4_2 = 0.f, e4_3 = 0.f;
    if (PASS == 1) {
        e4_0 = __ldg(embed + 0 * KCH + kb) * MS;
        e4_1 = __ldg(embed + 1 * KCH + kb) * MS;
        e4_2 = __ldg(embed + 2 * KCH + kb) * MS;
        e4_3 = __ldg(embed + 3 * KCH + kb) * MS;
    }

    float accE[9];
#pragma unroll
    for (int i = 0; i < 9; i++) accE[i] = 0.f;
    int cur_c = -1;

#define FLUSHE()                                                                \
    do {                                                                        \
        float* fb = ((PASS == 1) ? g_feats : g_new) + cur_c * FEAT + kb;        \
        _Pragma("unroll")                                                       \
        for (int comp = 0; comp < 9; comp++)                                    \
            atomicAdd(fb + comp * KCH, accE[comp]);                             \
    } while (0)

    for (int tile = blockIdx.x; tile < NTILES; tile += gridDim.x) {
        const int q0 = tile * 16;

        /* stage the 16 records (3 float4 each) into smem once per tile */
        if (threadIdx.x < 48)
            recs[threadIdx.x] = __ldg(g_rec + (u64)q0 * 3 + threadIdx.x);

        /* hidden layer: warp w handles pairs q0+4w .. q0+4w+3 */
        float hac[4];
#pragma unroll
        for (int pp = 0; pp < 4; pp++) {
            const float4* rr = g_rad + (q0 + 4 * w + pp) * 2;
            const float4 i0 = __ldg(rr + 0);
            const float4 i1 = __ldg(rr + 1);
            float h = b1s[lane]
                + i0.x * w1s[lane]        + i0.y * w1s[32 + lane]
                + i0.z * w1s[64 + lane]   + i0.w * w1s[96 + lane]
                + i1.x * w1s[128 + lane]  + i1.y * w1s[160 + lane]
                + i1.z * w1s[192 + lane]  + i1.w * w1s[224 + lane];
            hac[pp] = siluf(h);
        }
        hs[(2 * w + 0) * 32 + lane] = pk2(hac[0], hac[1]);
        hs[(2 * w + 1) * 32 + lane] = pk2(hac[2], hac[3]);
        __syncthreads();

        /* GEMM: 16 pairs (8 packed) x 3 rows for this warp's channels */
        u64 A0[8], A1[8], A2[8];
#pragma unroll
        for (int j = 0; j < 8; j++) { A0[j] = bi0; A1[j] = bi1; A2[j] = bi2; }
#pragma unroll 8
        for (int b = 0; b < 32; b++) {
            const float w0f = w2s[b * 384 + kb];
            const float w1f = w2s[b * 384 + 128 + kb];
            const float w2f = w2s[b * 384 + 256 + kb];
            const u64 wv0 = pk2(w0f, w0f);
            const u64 wv1 = pk2(w1f, w1f);
            const u64 wv2 = pk2(w2f, w2f);
#pragma unroll
            for (int j = 0; j < 8; j++) {
                const u64 hb = hs[j * 32 + b];
                fma2(A0[j], wv0, hb);
                fma2(A1[j], wv1, hb);
                fma2(A2[j], wv2, hb);
            }
        }

        /* epilogue: all 16 pairs from smem-staged records */
#pragma unroll
        for (int j = 0; j < 8; j++) {
            float r0v[2], r1v[2], r2v[2];
            upk2(r0v[0], r0v[1], A0[j]);
            upk2(r1v[0], r1v[1], A1[j]);
            upk2(r2v[0], r2v[1], A2[j]);
#pragma unroll
            for (int e = 0; e < 2; e++) {
                const int pidx = 2 * j + e;
                const float4 a0 = recs[pidx * 3 + 0];
                const float4 s1 = recs[pidx * 3 + 1];
                const float4 s2 = recs[pidx * 3 + 2];
                const int c = __float_as_int(a0.x);
                const int n = __float_as_int(a0.y);
                const int sp = __float_as_int(a0.z);
                const float sh6 = a0.w;
                const float sh1 = s1.x, sh2 = s1.y, sh3 = s1.z, sh4 = s1.w;
                const float sh5 = s2.x, sh7 = s2.y, sh8 = s2.z;

                if (c != cur_c) {
                    if (cur_c >= 0) FLUSHE();
                    cur_c = c;
#pragma unroll
                    for (int i = 0; i < 9; i++) accE[i] = 0.f;
                }

                if (PASS == 1) {
                    const float e_ = (sp == 0) ? e4_0 : (sp == 1) ? e4_1 : (sp == 2) ? e4_2 : e4_3;
                    const float r0 = r0v[e] * e_, r1 = r1v[e] * e_, r2 = r2v[e] * e_;
                    accE[0] += ISC * r0;
                    accE[1] += sh1 * r1;
                    accE[2] += sh2 * r1;
                    accE[3] += sh3 * r1;
                    accE[4] += sh4 * r2;
                    accE[5] += sh5 * r2;
                    accE[6] += sh6 * r2;
                    accE[7] += sh7 * r2;
                    accE[8] += sh8 * r2;
                } else {
                    const float r0 = r0v[e] * MS, r1 = r1v[e] * MS, r2 = r2v[e] * MS;
                    const float* gn = g_feats + n * FEAT;
                    const float inv = __ldg(gn + kb);
                    const float u1 = r1 * inv, u2 = r2 * inv;
                    accE[0] += (1.f + ISC) * r0 * inv;
                    accE[1] += sh1 * u1 + r0 * __ldg(gn + 1 * KCH + kb);
                    accE[2] += sh2 * u1 + r0 * __ldg(gn + 2 * KCH + kb);
                    accE[3] += sh3 * u1 + r0 * __ldg(gn + 3 * KCH + kb);
                    accE[4] += sh4 * u2 + r0 * __ldg(gn + 4 * KCH + kb);
                    accE[5] += sh5 * u2 + r0 * __ldg(gn + 5 * KCH + kb);
                    accE[6] += sh6 * u2 + r0 * __ldg(gn + 6 * KCH + kb);
                    accE[7] += sh7 * u2 + r0 * __ldg(gn + 7 * KCH + kb);
                    accE[8] += sh8 * u2 + r0 * __ldg(gn + 8 * KCH + kb);
                }
            }
        }
        __syncthreads();   /* protect hs + recs before next tile */
    }
    if (cur_c >= 0) FLUSHE();
#undef FLUSHE
}

/* ---------------- CG tensor-square iterate (per atom, per k) ---------------- */
template <int BUF>
__global__ __launch_bounds__(128)
void cg_kernel(const float* __restrict__ mix, const float* __restrict__ U2g)
{
    __shared__ float U[81];
    const int k = threadIdx.x;
    if (k < 81) U[k] = U2g[k];
    __syncthreads();
    float* base = ((BUF == 0) ? g_feats : g_new) + blockIdx.x * FEAT + k;
    float* dup  = g_new + blockIdx.x * FEAT + k;

    {
        const float f0 = base[0];
        const float v = f0 + __ldg(mix + k) * f0 * f0;
        base[0] = v;
        if (BUF == 0) dup[0] = v;
    }
    {
        float f1[3];
#pragma unroll
        for (int j = 0; j < 3; j++) f1[j] = base[(1 + j) * KCH];
        float Mv[9];
#pragma unroll
        for (int q = 0; q < 9; q++)
            Mv[q] = U[9 + q] * f1[0] + U[18 + q] * f1[1] + U[27 + q] * f1[2];
        float Cm[9];
#pragma unroll
        for (int i = 0; i < 3; i++)
#pragma unroll
            for (int j = 0; j < 3; j++)
                Cm[3 * i + j] = Mv[3 * i] * Mv[j] + Mv[3 * i + 1] * Mv[3 + j] + Mv[3 * i + 2] * Mv[6 + j];
        const float m1 = __ldg(mix + KCH + k);
        float B[9];
#pragma unroll
        for (int q = 0; q < 9; q++) B[q] = Mv[q] + m1 * Cm[q];
#pragma unroll
        for (int j = 0; j < 3; j++) {
            float o = 0.f;
#pragma unroll
            for (int q = 0; q < 9; q++) o += U[(1 + j) * 9 + q] * B[q];
            base[(1 + j) * KCH] = o;
            if (BUF == 0) dup[(1 + j) * KCH] = o;
        }
    }
    {
        float f2[5];
#pragma unroll
        for (int j = 0; j < 5; j++) f2[j] = base[(4 + j) * KCH];
        float Mv[9];
#pragma unroll
        for (int q = 0; q < 9; q++)
            Mv[q] = U[36 + q] * f2[0] + U[45 + q] * f2[1] + U[54 + q] * f2[2] + U[63 + q] * f2[3] + U[72 + q] * f2[4];
        float Cm[9];
#pragma unroll
        for (int i = 0; i < 3; i++)
#pragma unroll
            for (int j = 0; j < 3; j++)
                Cm[3 * i + j] = Mv[3 * i] * Mv[j] + Mv[3 * i + 1] * Mv[3 + j] + Mv[3 * i + 2] * Mv[6 + j];
        const float m2 = __ldg(mix + 2 * KCH + k);
        float B[9];
#pragma unroll
        for (int q = 0; q < 9; q++) B[q] = Mv[q] + m2 * Cm[q];
#pragma unroll
        for (int j = 0; j < 5; j++) {
            float o = 0.f;
#pragma unroll
            for (int q = 0; q < 9; q++) o += U[(4 + j) * 9 + q] * B[q];
            base[(4 + j) * KCH] = o;
            if (BUF == 0) dup[(4 + j) * KCH] = o;
        }
    }
}

/* ---------------- head MLP: 20 atoms per block ---------------- */
#define APB 20
__global__ __launch_bounds__(128)
void head_kernel(const float* __restrict__ hw1, const float* __restrict__ hb1,
                 const float* __restrict__ hw2, const float* __restrict__ hb2,
                 const float* __restrict__ lw, const float* __restrict__ lb,
                 float* __restrict__ out)
{
    __shared__ float hs[APB][132];
    const int a0 = blockIdx.x * APB;
    const int j = threadIdx.x;

    for (int i = 0; i < APB; i++) hs[i][j] = g_new[(a0 + i) * FEAT + j];
    __syncthreads();

    float acc[APB];
    {
        const float b = __ldg(hb1 + j);
#pragma unroll
        for (int i = 0; i < APB; i++) acc[i] = b;
    }
    for (int kk = 0; kk < 128; kk++) {
        const float w = __ldg(hw1 + kk * 128 + j);
#pragma unroll
        for (int i = 0; i < APB; i++) acc[i] += hs[i][kk] * w;
    }
    __syncthreads();
#pragma unroll
    for (int i = 0; i < APB; i++) hs[i][j] = siluf(acc[i]);
    __syncthreads();
    {
        const float b = __ldg(hb2 + j);
#pragma unroll
        for (int i = 0; i < APB; i++) acc[i] = b;
    }
    for (int kk = 0; kk < 128; kk++) {
        const float w = __ldg(hw2 + kk * 128 + j);
#pragma unroll
        for (int i = 0; i < APB; i++) acc[i] += hs[i][kk] * w;
    }
    __syncthreads();
    {
        const float lwj = __ldg(lw + j);
#pragma unroll
        for (int i = 0; i < APB; i++) hs[i][j] = siluf(acc[i]) * lwj;
    }
    __syncthreads();
    if (j < APB) {
        float s = __ldg(lb);
        for (int q = 0; q < 128; q++) s += hs[j][q];
        out[a0 + j] = s;
    }
}

extern "C" void kernel_launch(void* const* d_in, const int* in_sizes, int n_in,
                              void* d_out, int out_size)
{
    const float* pos     = (const float*)d_in[0];
    const float* cells   = (const float*)d_in[1];
    const int*   species = (const int*)d_in[2];
    const int*   shifts  = (const int*)d_in[3];
    const int*   ctr     = (const int*)d_in[4];
    const int*   nbr     = (const int*)d_in[5];
    const int*   spair   = (const int*)d_in[6];
    const float* embed   = (const float*)d_in[7];
    const float* rw1 = (const float*)d_in[8];
    const float* rb1 = (const float*)d_in[9];
    const float* rw2 = (const float*)d_in[10];
    const float* rb2 = (const float*)d_in[11];
    const float* ew1 = (const float*)d_in[12];
    const float* eb1 = (const float*)d_in[13];
    const float* ew2 = (const float*)d_in[14];
    const float* eb2 = (const float*)d_in[15];
    const float* mixa  = (const float*)d_in[16];
    const float* emixa = (const float*)d_in[17];
    const float* hw1 = (const float*)d_in[18];
    const float* hb1 = (const float*)d_in[19];
    const float* hw2 = (const float*)d_in[20];
    const float* hb2 = (const float*)d_in[21];
    const float* lw  = (const float*)d_in[22];
    const float* lb  = (const float*)d_in[23];
    const float* U2  = (const float*)d_in[24];
    float* out = (float*)d_out;

    zero_kernel<<<1024, 256>>>();
    histscan_kernel<<<1, 1024>>>(ctr);
    scatter_kernel<<<(NPAIRS + 255) / 256, 256>>>(pos, cells, species, shifts, ctr, nbr, spair);
    pair_kernel<1><<<592, 128>>>(embed, rw1, rb1, rw2, rb2);   /* launch idx 3 -> ncu capture */
    cg_kernel<0><<<NATOMS, 128>>>(mixa, U2);
    pair_kernel<2><<<592, 128>>>(embed, ew1, eb1, ew2, eb2);
    cg_kernel<1><<<NATOMS, 128>>>(emixa, U2);
    head_kernel<<<NATOMS / APB, 128>>>(hw1, hb1, hw2, hb2, lw, lb, out);
}